// round 7
// baseline (speedup 1.0000x reference)
#include <cuda_runtime.h>
#include <cuda_bf16.h>
#include <cstdint>

#define NN 2048
#define NROWS 16384
#define TILE 32
#define NTILES 64            // 2048 / 32
#define WARPS 4              // warps per block
#define PAD 36               // smem row stride (floats): 16B-aligned, conflict-free

__device__ __align__(8) float2 g_csn[NN];   // (cos, sin)

__global__ void rg_sincos_kernel(const float* __restrict__ angles) {
    int k = blockIdx.x * blockDim.x + threadIdx.x;
    if (k < NN) {
        float s, c;
        sincosf(angles[k], &s, &c);
        g_csn[k] = make_float2(c, s);
    }
}

// One lane = one row. Warp = 32 consecutive rows, streaming k in 32-wide tiles
// (descending), carry in a register. Transposes via per-warp smem (pad 36,
// float4 both directions, conflict-free). Delayed aligned y stores.
__global__ __launch_bounds__(128)
void rg_givens_kernel(const float* __restrict__ x, float* __restrict__ y) {
    __shared__ float xbuf[WARPS][32 * PAD];
    __shared__ float ybuf[WARPS][32 * PAD];

    const int l   = threadIdx.x & 31;
    const int wid = threadIdx.x >> 5;
    const int g   = blockIdx.x * WARPS + wid;       // row-group 0..511
    const long rowbase = (long)g * 32;

    float* xb = xbuf[wid];
    float* yb = ybuf[wid];

    const int lr = l >> 3;      // row-sub 0..3
    const int lc = l & 7;       // col-sub 0..7
    const float* xg = x + (rowbase + lr) * NN + lc * 4;   // tile-load base
    float*       yg = y + (rowbase + lr) * NN + lc * 4;   // tile-store base
    const float* xrow_my = x + (rowbase + l) * NN;        // this lane's row

    // Row scalars: carry enters at k=2047 with value x[0]; x~[0] = w0.
    float x0 = xrow_my[0];
    float xT = xrow_my[NN - 1];
    float2 csT = __ldg(&g_csn[NN - 1]);
    float w0 = fmaf(csT.y, xT, csT.x * x0);
    float carry = x0;

    float4 pf[8];
    // Prologue: tile 63 -> xbuf; prefetch tile 62 -> pf
    {
        const float* p = xg + 63 * TILE;
        #pragma unroll
        for (int i = 0; i < 8; i++) pf[i] = *(const float4*)(p + (size_t)i * 4 * NN);
        #pragma unroll
        for (int i = 0; i < 8; i++)
            *(float4*)&xb[(i * 4 + lr) * PAD + lc * 4] = pf[i];
        const float* p2 = xg + 62 * TILE;
        #pragma unroll
        for (int i = 0; i < 8; i++) pf[i] = *(const float4*)(p2 + (size_t)i * 4 * NN);
    }
    __syncwarp();

    float xv[32];
    for (int t = NTILES - 1; t >= 0; t--) {
        const int K = t * TILE;

        // (a) bulk LDS: my row's 32 elements -> registers
        #pragma unroll
        for (int q = 0; q < 8; q++) {
            float4 v = *(const float4*)&xb[l * PAD + q * 4];
            xv[4 * q + 0] = v.x; xv[4 * q + 1] = v.y;
            xv[4 * q + 2] = v.z; xv[4 * q + 3] = v.w;
        }
        __syncwarp();

        // (b) stage tile t-1 into xbuf; prefetch tile t-2
        if (t >= 1) {
            #pragma unroll
            for (int i = 0; i < 8; i++)
                *(float4*)&xb[(i * 4 + lr) * PAD + lc * 4] = pf[i];
            if (t >= 2) {
                const float* p = xg + (t - 2) * TILE;
                #pragma unroll
                for (int i = 0; i < 8; i++) pf[i] = *(const float4*)(p + (size_t)i * 4 * NN);
            }
        }
        if (t == 0) xv[0] = w0;    // substitute x~[0]

        // (c) step tt=31: out = y[K+32] = slot0 of the tile above; then store it
        {
            float2 cs = __ldg(&g_csn[K + 31]);
            float out = fmaf(cs.x, carry, cs.y * xv[31]);
            carry = fmaf(-cs.y, carry, cs.x * xv[31]);
            if (t < NTILES - 1) {
                yb[l * PAD + 0] = out;
                __syncwarp();
                #pragma unroll
                for (int i = 0; i < 8; i++) {
                    float4 v = *(const float4*)&yb[(i * 4 + lr) * PAD + lc * 4];
                    *(float4*)(yg + (size_t)i * 4 * NN + (K + 32)) = v;
                }
                __syncwarp();
            }
            // t == 63: out(2047) discarded (no y[2048])
        }

        // (d) steps tt=30..0: out(K+tt) = y[K+tt+1] -> xv[tt+1] (xv[tt+1] already consumed)
        #pragma unroll
        for (int tt = 30; tt >= 0; tt--) {
            float2 cs = __ldg(&g_csn[K + tt]);
            float out = fmaf(cs.x, carry, cs.y * xv[tt]);
            carry = fmaf(-cs.y, carry, cs.x * xv[tt]);
            xv[tt + 1] = out;
        }
        // quad-STS outs into ybuf slots (slot0 is dummy, filled by next tile / epilogue)
        #pragma unroll
        for (int q = 0; q < 8; q++) {
            float4 v = make_float4(xv[4 * q], xv[4 * q + 1], xv[4 * q + 2], xv[4 * q + 3]);
            *(float4*)&yb[l * PAD + q * 4] = v;
        }
        __syncwarp();
    }

    // Epilogue: slot0 = y[0] = exit carry; store y[0..31]
    yb[l * PAD + 0] = carry;
    __syncwarp();
    #pragma unroll
    for (int i = 0; i < 8; i++) {
        float4 v = *(const float4*)&yb[(i * 4 + lr) * PAD + lc * 4];
        *(float4*)(yg + (size_t)i * 4 * NN) = v;
    }
}

extern "C" void kernel_launch(void* const* d_in, const int* in_sizes, int n_in,
                              void* d_out, int out_size) {
    const float* x      = (const float*)d_in[0];   // [16384, 2048] fp32
    const float* angles = (const float*)d_in[1];   // [2048] fp32
    float* y = (float*)d_out;                      // [16384, 2048] fp32

    (void)in_sizes; (void)n_in; (void)out_size;

    rg_sincos_kernel<<<(NN + 255) / 256, 256>>>(angles);
    rg_givens_kernel<<<NROWS / (32 * WARPS), 32 * WARPS>>>(x, y);
}

// round 9
// speedup vs baseline: 1.3047x; 1.3047x over previous
#include <cuda_runtime.h>
#include <cuda_bf16.h>
#include <cstdint>

#define NN 2048
#define NROWS 16384
#define ROWS_CONC 4          // rows in flight per block
#define ITER 8               // row-sets per block
#define THREADS 512          // 16 warps: 4 warps per row
#define CHUNK 16
// padded layout: p(k) = k + (k>>5); row stride = 2048 + 64 = 2112 words
#define PADSTRIDE 2112
#define PTOP 2110            // p(2047)

__device__ float g_cs[NN];
__device__ float g_sn[NN];

__global__ void rg_sincos_kernel(const float* __restrict__ angles) {
    int k = blockIdx.x * blockDim.x + threadIdx.x;
    if (k < NN) {
        float s, c;
        sincosf(angles[k], &s, &c);
        g_cs[k] = c;
        g_sn[k] = s;
    }
}

// 4 warps/row, chunk-16 affine scan; cos/sin tables in REGISTERS (loaded once),
// 8 row-sets per block with double-buffered smem staging + register prefetch.
__global__ __launch_bounds__(THREADS, 2)
void rg_givens_kernel(const float* __restrict__ x, float* __restrict__ y) {
    extern __shared__ float sm[];
    float* buf0 = sm;                                    // [4][PADSTRIDE]
    float* buf1 = sm + ROWS_CONC * PADSTRIDE;            // [4][PADSTRIDE]
    float* wmA  = buf1 + ROWS_CONC * PADSTRIDE;          // [4 rows][4 warps]
    float* wmB  = wmA + 16;

    const int tid  = threadIdx.x;
    const int lane = tid & 31;
    const int w    = tid >> 5;
    const int rib  = w >> 2;           // row in set
    const int h    = w & 3;            // quarter of row
    const long base = (long)blockIdx.x * (ROWS_CONC * ITER);

    // ---- one-time: chunk tables into registers ----
    const int C = h * 32 + lane;       // chunk id 0..127 (row-independent)
    const int kb = 16 * C;
    float rc[CHUNK], rs[CHUNK];
    #pragma unroll
    for (int t = 0; t < CHUNK; t++) {
        rc[t] = g_cs[kb + t];
        rs[t] = g_sn[kb + t];
    }
    float Bm = 1.0f;
    #pragma unroll
    for (int t = 0; t < CHUNK; t++) Bm *= -rs[t];
    const float cTop = g_cs[NN - 1];
    const float sTop = g_sn[NN - 1];

    const int pbase = 16 * C + (C >> 1);
    const int pnext = 16 * (C + 1) + ((C + 1) >> 1);

    // ---- prologue: stage row-set 0 into buf0 ----
    {
        const float* xrow = x + (base + rib) * NN;
        float* xr = buf0 + rib * PADSTRIDE;
        #pragma unroll
        for (int i = 0; i < 4; i++) {
            int v4 = h * 128 + i * 32 + lane;
            float4 val = *(const float4*)(xrow + v4 * 4);
            int k = v4 * 4;
            int p = k + (k >> 5);
            xr[p + 0] = val.x; xr[p + 1] = val.y;
            xr[p + 2] = val.z; xr[p + 3] = val.w;
        }
    }
    __syncthreads();

    for (int it = 0; it < ITER; it++) {
        float* xr = ((it & 1) ? buf1 : buf0) + rib * PADSTRIDE;
        const long row = base + it * ROWS_CONC + rib;

        // ---- load chunk x into registers (conflict-free scalar LDS) ----
        float xv[CHUNK];
        #pragma unroll
        for (int t = 0; t < CHUNK; t++) xv[t] = xr[pbase + t];
        const float x0 = xr[0];
        if (C == 0) {
            // x~[0] = w0 = s_top*x[2047] + c_top*x[0]
            xv[0] = fmaf(sTop, xr[PTOP], cTop * x0);
        }

        // ---- stage 2: chunk affine map (tables from regs) ----
        float A = 0.0f;
        #pragma unroll
        for (int t = CHUNK - 1; t >= 0; t--) {
            A = fmaf(-rs[t], A, rc[t] * xv[t]);
        }

        // ---- warp suffix scan ----
        float gA = A, gB = Bm;
        #pragma unroll
        for (int d = 1; d < 32; d <<= 1) {
            float A2 = __shfl_down_sync(0xffffffffu, gA, d);
            float B2 = __shfl_down_sync(0xffffffffu, gB, d);
            if (lane + d < 32) {
                gA = fmaf(gB, A2, gA);
                gB = gB * B2;
            }
        }
        float nA = __shfl_down_sync(0xffffffffu, gA, 1);
        float nB = __shfl_down_sync(0xffffffffu, gB, 1);
        if (lane == 0) {
            wmA[rib * 4 + h] = gA;
            wmB[rib * 4 + h] = gB;
        }
        __syncthreads();

        float cin = x0;
        #pragma unroll
        for (int j = 3; j >= 1; j--) {
            if (j > h) cin = fmaf(wmB[rib * 4 + j], cin, wmA[rib * 4 + j]);
        }
        float carry = (lane == 31) ? cin : fmaf(nB, cin, nA);

        // ---- stage 3: replay; write y in place ----
        #pragma unroll
        for (int t = CHUNK - 1; t >= 0; t--) {
            float out = fmaf(rc[t], carry, rs[t] * xv[t]);
            carry = fmaf(-rs[t], carry, rc[t] * xv[t]);
            if (t == CHUNK - 1) {
                if (C != 127) xr[pnext] = out;   // y[16(C+1)]
            } else {
                xr[pbase + t + 1] = out;         // y[16C+t+1]
            }
        }
        if (C == 0) xr[0] = carry;               // y[0]

        // ---- prefetch next row-set (xv regs dead now) ----
        float4 pf0, pf1, pf2, pf3;
        if (it + 1 < ITER) {
            const float* xn = x + (base + (it + 1) * ROWS_CONC + rib) * NN;
            pf0 = *(const float4*)(xn + (h * 128 +  0 + lane) * 4);
            pf1 = *(const float4*)(xn + (h * 128 + 32 + lane) * 4);
            pf2 = *(const float4*)(xn + (h * 128 + 64 + lane) * 4);
            pf3 = *(const float4*)(xn + (h * 128 + 96 + lane) * 4);
        }
        __syncthreads();   // y complete in xr

        // ---- store y: padded smem -> coalesced float4 STG ----
        float* yrow = y + row * NN;
        #pragma unroll
        for (int i = 0; i < 4; i++) {
            int v4 = h * 128 + i * 32 + lane;
            int k = v4 * 4;
            int p = k + (k >> 5);
            float4 val;
            val.x = xr[p + 0]; val.y = xr[p + 1];
            val.z = xr[p + 2]; val.w = xr[p + 3];
            *(float4*)(yrow + v4 * 4) = val;
        }

        // ---- stage prefetched set into the other buffer ----
        if (it + 1 < ITER) {
            float* xr2 = (((it + 1) & 1) ? buf1 : buf0) + rib * PADSTRIDE;
            #pragma unroll
            for (int i = 0; i < 4; i++) {
                float4 val = (i == 0) ? pf0 : (i == 1) ? pf1 : (i == 2) ? pf2 : pf3;
                int k = (h * 128 + i * 32 + lane) * 4;
                int p = k + (k >> 5);
                xr2[p + 0] = val.x; xr2[p + 1] = val.y;
                xr2[p + 2] = val.z; xr2[p + 3] = val.w;
            }
        }
        __syncthreads();
    }
}

extern "C" void kernel_launch(void* const* d_in, const int* in_sizes, int n_in,
                              void* d_out, int out_size) {
    const float* x      = (const float*)d_in[0];   // [16384, 2048] fp32
    const float* angles = (const float*)d_in[1];   // [2048] fp32
    float* y = (float*)d_out;                      // [16384, 2048] fp32

    (void)in_sizes; (void)n_in; (void)out_size;

    rg_sincos_kernel<<<(NN + 255) / 256, 256>>>(angles);

    const int smem_bytes = (2 * ROWS_CONC * PADSTRIDE + 32) * sizeof(float);
    static bool attr_set = false;
    if (!attr_set) {
        cudaFuncSetAttribute(rg_givens_kernel,
                             cudaFuncAttributeMaxDynamicSharedMemorySize, smem_bytes);
        attr_set = true;
    }
    rg_givens_kernel<<<NROWS / (ROWS_CONC * ITER), THREADS, smem_bytes>>>(x, y);
}

// round 10
// speedup vs baseline: 1.8049x; 1.3834x over previous
#include <cuda_runtime.h>
#include <cuda_bf16.h>
#include <cstdint>

#define NN 2048
#define NROWS 16384
#define ROWS 8               // rows per block
#define THREADS 1024         // 32 warps: 4 warps per row
#define CHUNK 16
// padded layout: p(k) = k + (k>>5); row stride = 2048 + 64 = 2112 words
#define PADSTRIDE 2112
#define PTOP 2110            // p(2047)

// Single fused kernel: in-block sincos tables, register wA stage-2 weights,
// 4 warps/row chunk-16 affine scan, 8 rows per 1024-thread block.
__global__ __launch_bounds__(THREADS, 1)
void rg_givens_kernel(const float* __restrict__ x,
                      const float* __restrict__ angles,
                      float* __restrict__ y) {
    extern __shared__ float sm[];
    float* xs  = sm;                              // [8][PADSTRIDE]
    float* c_s = sm + ROWS * PADSTRIDE;           // [PADSTRIDE]
    float* s_s = c_s + PADSTRIDE;                 // [PADSTRIDE]
    float* wmA = s_s + PADSTRIDE;                 // [8 rows][4 warps]
    float* wmB = wmA + ROWS * 4;

    const int tid  = threadIdx.x;
    const int lane = tid & 31;
    const int w    = tid >> 5;
    const int rib  = w >> 2;          // row in block (0..7)
    const int h    = w & 3;           // quarter of row
    const long row = (long)blockIdx.x * ROWS + rib;
    float* xr = xs + rib * PADSTRIDE;

    // ---- Phase 1a: sincos tables into padded smem (2 angles/thread) ----
    #pragma unroll
    for (int k = tid; k < NN; k += THREADS) {
        float s, c;
        sincosf(angles[k], &s, &c);
        int p = k + (k >> 5);
        c_s[p] = c;
        s_s[p] = s;
    }
    // ---- Phase 1b: stage x rows (coalesced float4 LDG, scalar STS) ----
    const float* xrow = x + row * NN;
    float4 v0, v1, v2, v3;
    {
        v0 = *(const float4*)(xrow + (h * 128 +  0 + lane) * 4);
        v1 = *(const float4*)(xrow + (h * 128 + 32 + lane) * 4);
        v2 = *(const float4*)(xrow + (h * 128 + 64 + lane) * 4);
        v3 = *(const float4*)(xrow + (h * 128 + 96 + lane) * 4);
        #pragma unroll
        for (int i = 0; i < 4; i++) {
            float4 val = (i == 0) ? v0 : (i == 1) ? v1 : (i == 2) ? v2 : v3;
            int k = (h * 128 + i * 32 + lane) * 4;
            int p = k + (k >> 5);
            xr[p + 0] = val.x; xr[p + 1] = val.y;
            xr[p + 2] = val.z; xr[p + 3] = val.w;
        }
    }
    __syncthreads();

    // ---- Phase 2: build per-chunk stage-2 weights in registers ----
    const int C = h * 32 + lane;                 // chunk id 0..127
    const int pbase = 16 * C + (C >> 1);
    const int pnext = 16 * (C + 1) + ((C + 1) >> 1);
    float wAr[CHUNK];
    float Bm = 1.0f;
    #pragma unroll
    for (int t = 0; t < CHUNK; t++) {
        float ct = c_s[pbase + t];
        float st = s_s[pbase + t];
        wAr[t] = Bm * ct;        // c_t * prod_{v<t}(-s_v)
        Bm = -st * Bm;
    }

    // ---- Load chunk x into registers (conflict-free scalar LDS) ----
    float xv[CHUNK];
    #pragma unroll
    for (int t = 0; t < CHUNK; t++) xv[t] = xr[pbase + t];
    const float x0 = xr[0];
    if (C == 0) {
        // x~[0] = w0 = s_top*x[2047] + c_top*x[0]
        xv[0] = fmaf(s_s[PTOP], xr[PTOP], c_s[PTOP] * x0);
    }

    // ---- Stage 2: chunk affine map as dot product (ILP-4) ----
    float A0 = 0.f, A1 = 0.f, A2 = 0.f, A3 = 0.f;
    #pragma unroll
    for (int t = 0; t < CHUNK; t += 4) {
        A0 = fmaf(wAr[t + 0], xv[t + 0], A0);
        A1 = fmaf(wAr[t + 1], xv[t + 1], A1);
        A2 = fmaf(wAr[t + 2], xv[t + 2], A2);
        A3 = fmaf(wAr[t + 3], xv[t + 3], A3);
    }
    float A = (A0 + A1) + (A2 + A3);

    // ---- Warp suffix scan of affine maps ----
    float gA = A, gB = Bm;
    #pragma unroll
    for (int d = 1; d < 32; d <<= 1) {
        float A2s = __shfl_down_sync(0xffffffffu, gA, d);
        float B2s = __shfl_down_sync(0xffffffffu, gB, d);
        if (lane + d < 32) {
            gA = fmaf(gB, A2s, gA);
            gB = gB * B2s;
        }
    }
    float nA = __shfl_down_sync(0xffffffffu, gA, 1);
    float nB = __shfl_down_sync(0xffffffffu, gB, 1);
    if (lane == 0) {
        wmA[rib * 4 + h] = gA;
        wmB[rib * 4 + h] = gB;
    }
    __syncthreads();

    // entering carry for this warp = (W_{h+1} o ... o W_3)(x0)
    float cin = x0;
    #pragma unroll
    for (int j = 3; j >= 1; j--) {
        if (j > h) cin = fmaf(wmB[rib * 4 + j], cin, wmA[rib * 4 + j]);
    }
    float carry = (lane == 31) ? cin : fmaf(nB, cin, nA);

    // ---- Stage 3: replay (c,s from smem); write y in place ----
    #pragma unroll
    for (int t = CHUNK - 1; t >= 0; t--) {
        float lc = c_s[pbase + t];
        float ls = s_s[pbase + t];
        float out = fmaf(lc, carry, ls * xv[t]);
        carry = fmaf(-ls, carry, lc * xv[t]);
        if (t == CHUNK - 1) {
            if (C != 127) xr[pnext] = out;   // y[16(C+1)]
        } else {
            xr[pbase + t + 1] = out;         // y[16C+t+1]
        }
    }
    if (C == 0) xr[0] = carry;               // y[0]
    __syncthreads();

    // ---- Store: padded smem -> coalesced float4 STG ----
    float* yrow = y + row * NN;
    #pragma unroll
    for (int i = 0; i < 4; i++) {
        int v4 = h * 128 + i * 32 + lane;
        int k = v4 * 4;
        int p = k + (k >> 5);
        float4 val;
        val.x = xr[p + 0]; val.y = xr[p + 1];
        val.z = xr[p + 2]; val.w = xr[p + 3];
        *(float4*)(yrow + v4 * 4) = val;
    }
}

extern "C" void kernel_launch(void* const* d_in, const int* in_sizes, int n_in,
                              void* d_out, int out_size) {
    const float* x      = (const float*)d_in[0];   // [16384, 2048] fp32
    const float* angles = (const float*)d_in[1];   // [2048] fp32
    float* y = (float*)d_out;                      // [16384, 2048] fp32

    (void)in_sizes; (void)n_in; (void)out_size;

    const int smem_bytes = (ROWS * PADSTRIDE + 2 * PADSTRIDE + 2 * ROWS * 4) * sizeof(float);
    static bool attr_set = false;
    if (!attr_set) {
        cudaFuncSetAttribute(rg_givens_kernel,
                             cudaFuncAttributeMaxDynamicSharedMemorySize, smem_bytes);
        attr_set = true;
    }
    rg_givens_kernel<<<NROWS / ROWS, THREADS, smem_bytes>>>(x, angles, y);
}

// round 11
// speedup vs baseline: 2.0221x; 1.1203x over previous
#include <cuda_runtime.h>
#include <cuda_bf16.h>
#include <cstdint>

#define NN 2048
#define NROWS 16384
#define ROWS_PER_BLOCK 4
#define THREADS 512          // 16 warps: 4 warps per row
#define CHUNK 16
// padded layout: p(k) = k + (k>>5); row stride = 2048 + 64 = 2112 words
#define PADSTRIDE 2112
#define PTOP 2110            // p(2047)

__device__ float g_cs[NN];
__device__ float g_sn[NN];

__global__ void rg_sincos_kernel(const float* __restrict__ angles) {
    int k = blockIdx.x * blockDim.x + threadIdx.x;
    if (k < NN) {
        float s, c;
        sincosf(angles[k], &s, &c);
        g_cs[k] = c;
        g_sn[k] = s;
    }
}

// 4 warps/row, chunk-16 affine scan; x NOT register-cached (re-read from smem)
// to cut regs below 42 -> 3 blocks/SM -> 48 warps.
__global__ __launch_bounds__(THREADS, 3)
void rg_givens_kernel(const float* __restrict__ x, float* __restrict__ y) {
    extern __shared__ float sm[];
    float* xs  = sm;                                   // [4][PADSTRIDE]
    float* c_s = sm + ROWS_PER_BLOCK * PADSTRIDE;      // [PADSTRIDE]
    float* s_s = c_s + PADSTRIDE;                      // [PADSTRIDE]
    float* wmA = s_s + PADSTRIDE;                      // [4 rows][4 warps]
    float* wmB = wmA + 16;                             // [4 rows][4 warps]

    const int tid  = threadIdx.x;
    const int lane = tid & 31;
    const int w    = tid >> 5;
    const int rib  = w >> 2;          // row in block
    const int h    = w & 3;           // quarter of row
    const long row = (long)blockIdx.x * ROWS_PER_BLOCK + rib;
    float* xr = xs + rib * PADSTRIDE;

    // ---- Stage 1: staging ----
    const float* xrow = x + row * NN;
    #pragma unroll
    for (int i = 0; i < 4; i++) {
        int v4 = h * 128 + i * 32 + lane;
        float4 val = *(const float4*)(xrow + v4 * 4);
        int k = v4 * 4;
        int p = k + (k >> 5);
        xr[p + 0] = val.x;
        xr[p + 1] = val.y;
        xr[p + 2] = val.z;
        xr[p + 3] = val.w;
    }
    // cos/sin tables into padded smem (block-wide)
    #pragma unroll
    for (int k = tid; k < NN; k += THREADS) {
        int p = k + (k >> 5);
        c_s[p] = g_cs[k];
        s_s[p] = g_sn[k];
    }
    __syncthreads();

    const float x0 = xr[0];
    const int C = h * 32 + lane;       // chunk id 0..127
    const int pbase = 16 * C + (C >> 1);
    const int pnext = 16 * (C + 1) + ((C + 1) >> 1);

    // Pre-read boundary element (clobbered cross-lane in stage 3).
    // C==0 substitutes x~[0] = w0 = s_top*x[2047] + c_top*x[0].
    float xlo;
    if (C == 0) {
        xlo = fmaf(s_s[PTOP], xr[PTOP], c_s[PTOP] * x0);
    } else {
        xlo = xr[pbase];
    }

    // ---- Stage 2: chunk affine map (x re-read from smem) ----
    float A = 0.0f, Bm = 1.0f;
    #pragma unroll
    for (int t = CHUNK - 1; t >= 1; t--) {
        float xv = xr[pbase + t];
        float lc = c_s[pbase + t];
        float ls = s_s[pbase + t];
        A  = fmaf(-ls, A, lc * xv);
        Bm = -ls * Bm;
    }
    {   // t = 0 uses xlo
        float lc = c_s[pbase];
        float ls = s_s[pbase];
        A  = fmaf(-ls, A, lc * xlo);
        Bm = -ls * Bm;
    }

    // ---- Warp suffix scan of affine maps ----
    float gA = A, gB = Bm;
    #pragma unroll
    for (int d = 1; d < 32; d <<= 1) {
        float A2 = __shfl_down_sync(0xffffffffu, gA, d);
        float B2 = __shfl_down_sync(0xffffffffu, gB, d);
        if (lane + d < 32) {
            gA = fmaf(gB, A2, gA);
            gB = gB * B2;
        }
    }
    float nA = __shfl_down_sync(0xffffffffu, gA, 1);
    float nB = __shfl_down_sync(0xffffffffu, gB, 1);
    if (lane == 0) {
        wmA[rib * 4 + h] = gA;
        wmB[rib * 4 + h] = gB;
    }
    __syncthreads();

    // entering carry for this warp = (W_{h+1} o ... o W_3)(x0)
    float cin = x0;
    #pragma unroll
    for (int j = 3; j >= 1; j--) {
        if (j > h) cin = fmaf(wmB[rib * 4 + j], cin, wmA[rib * 4 + j]);
    }
    float carry = (lane == 31) ? cin : fmaf(nB, cin, nA);

    // ---- Stage 3: replay; re-read x from smem, write y in place ----
    // Own slots: read of slot t happens before own write to slot t+1 (descending),
    // and only slot 16C (xlo, pre-read) is written by another lane.
    #pragma unroll
    for (int t = CHUNK - 1; t >= 1; t--) {
        float xv = xr[pbase + t];
        float lc = c_s[pbase + t];
        float ls = s_s[pbase + t];
        float out = fmaf(lc, carry, ls * xv);
        carry = fmaf(-ls, carry, lc * xv);
        if (t == CHUNK - 1) {
            if (C != 127) xr[pnext] = out;   // y[16(C+1)]
        } else {
            xr[pbase + t + 1] = out;         // y[16C+t+1]
        }
    }
    {   // t = 0 uses xlo
        float lc = c_s[pbase];
        float ls = s_s[pbase];
        float out = fmaf(lc, carry, ls * xlo);
        carry = fmaf(-ls, carry, lc * xlo);
        xr[pbase + 1] = out;                 // y[16C+1]
    }
    if (C == 0) xr[0] = carry;               // y[0]
    __syncthreads();

    // ---- Store: padded smem -> coalesced float4 STG ----
    float* yrow = y + row * NN;
    #pragma unroll
    for (int i = 0; i < 4; i++) {
        int v4 = h * 128 + i * 32 + lane;
        int k = v4 * 4;
        int p = k + (k >> 5);
        float4 val;
        val.x = xr[p + 0];
        val.y = xr[p + 1];
        val.z = xr[p + 2];
        val.w = xr[p + 3];
        *(float4*)(yrow + v4 * 4) = val;
    }
}

extern "C" void kernel_launch(void* const* d_in, const int* in_sizes, int n_in,
                              void* d_out, int out_size) {
    const float* x      = (const float*)d_in[0];   // [16384, 2048] fp32
    const float* angles = (const float*)d_in[1];   // [2048] fp32
    float* y = (float*)d_out;                      // [16384, 2048] fp32

    (void)in_sizes; (void)n_in; (void)out_size;

    rg_sincos_kernel<<<(NN + 255) / 256, 256>>>(angles);

    const int smem_bytes = (ROWS_PER_BLOCK * PADSTRIDE + 2 * PADSTRIDE + 32) * sizeof(float);
    static bool attr_set = false;
    if (!attr_set) {
        cudaFuncSetAttribute(rg_givens_kernel,
                             cudaFuncAttributeMaxDynamicSharedMemorySize, smem_bytes);
        attr_set = true;
    }
    rg_givens_kernel<<<NROWS / ROWS_PER_BLOCK, THREADS, smem_bytes>>>(x, y);
}